// round 4
// baseline (speedup 1.0000x reference)
#include <cuda_runtime.h>

#define NN 50000
#define EE 800000
#define RR 4
#define CC 4
#define GG 512

// ---------------- device scratch (static, no allocation) ----------------
__device__ float g_W1[64 * 384];                    // [k][c], c: 0-255 rel, 256-319 root, 320-383 pad
__device__ float g_W2[64 * 384];
__device__ float g_h[(size_t)RR * NN * 64];         // per-relation transformed nodes
__device__ float g_agg1[(size_t)NN * 64];           // self+bias then += scaled messages
__device__ float g_agg2[(size_t)NN * 64];
__device__ float g_cnt[RR * NN];
__device__ float g_inv[RR * NN];
__device__ int   g_deg[NN];                         // total in-degree per dst
__device__ int   g_off[NN + 1];                     // CSR offsets
__device__ int   g_fill[NN];                        // placement cursors
__device__ unsigned g_eperm[EE];                    // packed (et<<16)|src, grouped by dst
__device__ float g_pool[GG * 64];
__device__ float g_pcnt[GG];

// ---------------- weight prep ----------------
__global__ void prep_w(const float* __restrict__ b1, const float* __restrict__ c1,
                       const float* __restrict__ r1, const float* __restrict__ b2,
                       const float* __restrict__ c2, const float* __restrict__ r2) {
    int t = blockIdx.x * blockDim.x + threadIdx.x;
    if (t >= 2 * 64 * 384) return;
    int layer = t / 24576;
    int i = t % 24576;
    int k = i / 384;
    int c = i % 384;
    const float* basis = layer ? b2 : b1;
    const float* comp  = layer ? c2 : c1;
    const float* root  = layer ? r2 : r1;
    float v = 0.f;
    if (c < 256) {
        int r = c >> 6, o = c & 63;
#pragma unroll
        for (int b = 0; b < 4; b++)
            v += comp[r * 4 + b] * basis[((size_t)b * 64 + k) * 64 + o];
    } else if (c < 320) {
        v = root[k * 64 + (c - 256)];
    }
    (layer ? g_W2 : g_W1)[k * 384 + c] = v;
}

// ---------------- zero the small accumulators ----------------
__global__ void zero_small() {
    int t = blockIdx.x * blockDim.x + threadIdx.x;
    int stride = gridDim.x * blockDim.x;
    for (int i = t; i < RR * NN; i += stride) g_cnt[i] = 0.f;
    for (int i = t; i < NN; i += stride) g_fill[i] = 0;
    for (int i = t; i < GG * 64; i += stride) g_pool[i] = 0.f;
    for (int i = t; i < GG; i += stride) g_pcnt[i] = 0.f;
}

// ---------------- per-(relation,dst) edge counts ----------------
__global__ void count_edges(const int* __restrict__ dst, const int* __restrict__ et) {
    int e = blockIdx.x * blockDim.x + threadIdx.x;
    if (e >= EE) return;
    atomicAdd(&g_cnt[et[e] * NN + dst[e]], 1.0f);
}

// ---------------- inv = 1/max(cnt,1); total degree per dst ----------------
__global__ void invert_cnt() {
    int i = blockIdx.x * blockDim.x + threadIdx.x;
    if (i < RR * NN) g_inv[i] = 1.0f / fmaxf(g_cnt[i], 1.0f);
    if (i < NN) {
        float s = g_cnt[i] + g_cnt[NN + i] + g_cnt[2 * NN + i] + g_cnt[3 * NN + i];
        g_deg[i] = (int)s;
    }
}

// ---------------- exclusive scan of g_deg -> g_off (single block) ----------------
__global__ void __launch_bounds__(1024) scan_deg() {
    __shared__ int sums[1024];
    const int CH = (NN + 1023) / 1024;     // 49
    int t = threadIdx.x;
    int base = t * CH;
    int local = 0;
    for (int i = 0; i < CH; i++) {
        int idx = base + i;
        if (idx < NN) local += g_deg[idx];
    }
    sums[t] = local;
    __syncthreads();
    for (int s = 1; s < 1024; s <<= 1) {
        int v = (t >= s) ? sums[t - s] : 0;
        __syncthreads();
        sums[t] += v;
        __syncthreads();
    }
    int running = sums[t] - local;          // exclusive prefix of this chunk
    for (int i = 0; i < CH; i++) {
        int idx = base + i;
        if (idx < NN) {
            g_off[idx] = running;
            running += g_deg[idx];
        }
    }
    if (t == 1023) g_off[NN] = sums[1023];
}

// ---------------- scatter edges into CSR order ----------------
__global__ void build_perm(const int* __restrict__ src, const int* __restrict__ dst,
                           const int* __restrict__ et) {
    int e = blockIdx.x * blockDim.x + threadIdx.x;
    if (e >= EE) return;
    int d = dst[e];
    int pos = g_off[d] + atomicAdd(&g_fill[d], 1);
    g_eperm[pos] = ((unsigned)et[e] << 16) | (unsigned)src[e];
}

// ---------------- SGEMM: [N,64] @ [64,384], 8x8 microtile -----------------
#define AS_PAD 132
__global__ void __launch_bounds__(256)
gemm128(const float* __restrict__ Xin, const float* __restrict__ bias, int layer) {
    extern __shared__ float smem[];
    float* As = smem;                 // [64][132]  As[k][m]
    float* Bs = smem + 64 * AS_PAD;   // [64][132]  Bs[k][c]
    const float* X = layer ? g_agg1 : Xin;
    const float* W = layer ? g_W2 : g_W1;
    float* aggOut = layer ? g_agg2 : g_agg1;
    const bool doRelu = (layer == 1);

    int t = threadIdx.x;
    int nodeBase = blockIdx.x * 128;
    int colTile = blockIdx.y;         // 0,1,2

#pragma unroll
    for (int i = 0; i < 8; i++) {
        int f = t + i * 256;
        int row = f >> 4;
        int k4 = (f & 15) << 2;
        int gn = nodeBase + row;
        float4 v = make_float4(0.f, 0.f, 0.f, 0.f);
        if (gn < NN) v = *(const float4*)(X + (size_t)gn * 64 + k4);
        if (doRelu) {
            v.x = fmaxf(v.x, 0.f); v.y = fmaxf(v.y, 0.f);
            v.z = fmaxf(v.z, 0.f); v.w = fmaxf(v.w, 0.f);
        }
        As[(k4 + 0) * AS_PAD + row] = v.x;
        As[(k4 + 1) * AS_PAD + row] = v.y;
        As[(k4 + 2) * AS_PAD + row] = v.z;
        As[(k4 + 3) * AS_PAD + row] = v.w;
    }
#pragma unroll
    for (int i = 0; i < 8; i++) {
        int f = t + i * 256;
        int k = f >> 5;
        int c4 = (f & 31) << 2;
        *(float4*)&Bs[k * AS_PAD + c4] =
            *(const float4*)(W + (size_t)k * 384 + colTile * 128 + c4);
    }
    __syncthreads();

    int tx = t & 15, ty = t >> 4;
    float acc[8][8];
#pragma unroll
    for (int i = 0; i < 8; i++)
#pragma unroll
        for (int j = 0; j < 8; j++) acc[i][j] = 0.f;

#pragma unroll
    for (int k = 0; k < 64; k++) {
        float4 a0 = *(const float4*)&As[k * AS_PAD + ty * 4];
        float4 a1 = *(const float4*)&As[k * AS_PAD + 64 + ty * 4];
        float4 b0 = *(const float4*)&Bs[k * AS_PAD + tx * 4];
        float4 b1 = *(const float4*)&Bs[k * AS_PAD + 64 + tx * 4];
        float av[8] = {a0.x, a0.y, a0.z, a0.w, a1.x, a1.y, a1.z, a1.w};
        float bv[8] = {b0.x, b0.y, b0.z, b0.w, b1.x, b1.y, b1.z, b1.w};
#pragma unroll
        for (int i = 0; i < 8; i++)
#pragma unroll
            for (int j = 0; j < 8; j++) acc[i][j] += av[i] * bv[j];
    }

    float4 bv4 = make_float4(0.f, 0.f, 0.f, 0.f);
    if (colTile == 2) bv4 = *(const float4*)(bias + tx * 4);

#pragma unroll
    for (int i = 0; i < 8; i++) {
        int gn = nodeBase + ((i < 4) ? (ty * 4 + i) : (64 + ty * 4 + i - 4));
        if (gn >= NN) continue;
#pragma unroll
        for (int j2 = 0; j2 < 2; j2++) {
            int cbase = colTile * 128 + j2 * 64 + tx * 4;
            if (cbase >= 320) continue;
            float4 v = make_float4(acc[i][j2 * 4 + 0], acc[i][j2 * 4 + 1],
                                   acc[i][j2 * 4 + 2], acc[i][j2 * 4 + 3]);
            int r = cbase >> 6, o = cbase & 63;
            if (r < 4) {
                *(float4*)(g_h + ((size_t)r * NN + gn) * 64 + o) = v;
            } else {
                v.x += bv4.x; v.y += bv4.y; v.z += bv4.z; v.w += bv4.w;
                *(float4*)(aggOut + (size_t)gn * 64 + o) = v;
            }
        }
    }
}

// ---------------- segmented aggregation: one warp per dst ----------------
// Lane l owns floats [2l, 2l+1] of the 64-wide row. No atomics: warp owns dst.
__global__ void __launch_bounds__(256) agg_edges(int layer) {
    int w = (blockIdx.x * blockDim.x + threadIdx.x) >> 5;
    if (w >= NN) return;
    int lane = threadIdx.x & 31;
    int beg = g_off[w], end = g_off[w + 1];
    float* agg = (layer ? g_agg2 : g_agg1) + (size_t)w * 64 + lane * 2;
    float2 acc0 = *(float2*)agg;                       // self + bias from GEMM
    float2 acc1 = make_float2(0.f, 0.f);

    int e = beg;
    for (; e + 1 < end; e += 2) {
        unsigned rs0 = g_eperm[e];
        unsigned rs1 = g_eperm[e + 1];
        int r0 = rs0 >> 16, s0 = rs0 & 0xFFFF;
        int r1 = rs1 >> 16, s1 = rs1 & 0xFFFF;
        float inv0 = g_inv[r0 * NN + w];
        float inv1 = g_inv[r1 * NN + w];
        float2 v0 = *(const float2*)(g_h + ((size_t)r0 * NN + s0) * 64 + lane * 2);
        float2 v1 = *(const float2*)(g_h + ((size_t)r1 * NN + s1) * 64 + lane * 2);
        acc0.x += v0.x * inv0; acc0.y += v0.y * inv0;
        acc1.x += v1.x * inv1; acc1.y += v1.y * inv1;
    }
    if (e < end) {
        unsigned rs = g_eperm[e];
        int r = rs >> 16, s = rs & 0xFFFF;
        float inv = g_inv[r * NN + w];
        float2 v = *(const float2*)(g_h + ((size_t)r * NN + s) * 64 + lane * 2);
        acc0.x += v.x * inv; acc0.y += v.y * inv;
    }
    acc0.x += acc1.x; acc0.y += acc1.y;
    *(float2*)agg = acc0;
}

// ---------------- final: relu(agg2), pool per graph ----------------
__global__ void pool_final(const int* __restrict__ batch) {
    int t = blockIdx.x * blockDim.x + threadIdx.x;
    int n = t >> 4;
    if (n >= NN) return;
    int j = t & 15;
    float4 o = *(const float4*)(g_agg2 + (size_t)n * 64 + j * 4);
    o.x = fmaxf(o.x, 0.f); o.y = fmaxf(o.y, 0.f);
    o.z = fmaxf(o.z, 0.f); o.w = fmaxf(o.w, 0.f);
    int g = batch[n];
    float* p = g_pool + g * 64 + j * 4;
    asm volatile("red.global.add.v4.f32 [%0], {%1,%2,%3,%4};"
                 :: "l"(p), "f"(o.x), "f"(o.y), "f"(o.z), "f"(o.w) : "memory");
    if (j == 0) atomicAdd(&g_pcnt[g], 1.0f);
}

// ---------------- classifier ----------------
__global__ void classify(const float* __restrict__ w, const float* __restrict__ b,
                         float* __restrict__ out) {
    int t = blockIdx.x * blockDim.x + threadIdx.x;
    if (t >= GG * CC) return;
    int g = t / CC, c = t % CC;
    float inv = 1.f / fmaxf(g_pcnt[g], 1.f);
    float acc = b[c];
#pragma unroll
    for (int k = 0; k < 64; k++)
        acc += g_pool[g * 64 + k] * inv * w[k * CC + c];
    out[t] = acc;
}

// ---------------- launch ----------------
extern "C" void kernel_launch(void* const* d_in, const int* in_sizes, int n_in,
                              void* d_out, int out_size) {
    const float* x      = (const float*)d_in[0];
    const int*   ei     = (const int*)d_in[1];
    const int*   et     = (const int*)d_in[2];
    const int*   batch  = (const int*)d_in[3];
    const float* basis1 = (const float*)d_in[4];
    const float* comp1  = (const float*)d_in[5];
    const float* root1  = (const float*)d_in[6];
    const float* bias1  = (const float*)d_in[7];
    const float* basis2 = (const float*)d_in[8];
    const float* comp2  = (const float*)d_in[9];
    const float* root2  = (const float*)d_in[10];
    const float* bias2  = (const float*)d_in[11];
    const float* clw    = (const float*)d_in[12];
    const float* clb    = (const float*)d_in[13];
    float* out = (float*)d_out;

    const int* src = ei;        // edge_index[0]
    const int* dstp = ei + EE;  // edge_index[1]

    static int smem_set = 0;
    const int GEMM_SMEM = 2 * 64 * AS_PAD * sizeof(float);   // 67584 B
    if (!smem_set) {
        cudaFuncSetAttribute(gemm128, cudaFuncAttributeMaxDynamicSharedMemorySize,
                             GEMM_SMEM);
        smem_set = 1;
    }

    dim3 ggrid((NN + 127) / 128, 3);

    // ---- per-launch preprocessing (shared by both layers) ----
    zero_small<<<256, 256>>>();
    prep_w<<<192, 256>>>(basis1, comp1, root1, basis2, comp2, root2);
    count_edges<<<EE / 256, 256>>>(dstp, et);
    invert_cnt<<<(RR * NN + 255) / 256, 256>>>();
    scan_deg<<<1, 1024>>>();
    build_perm<<<EE / 256, 256>>>(src, dstp, et);

    // ---- layer 1 ----
    gemm128<<<ggrid, 256, GEMM_SMEM>>>(x, bias1, 0);
    agg_edges<<<(NN * 32 + 255) / 256, 256>>>(0);

    // ---- layer 2 ----
    gemm128<<<ggrid, 256, GEMM_SMEM>>>(x, bias2, 1);
    agg_edges<<<(NN * 32 + 255) / 256, 256>>>(1);

    // ---- pool + classifier ----
    pool_final<<<(NN * 16) / 256, 256>>>(batch);
    classify<<<(GG * CC + 255) / 256, 256>>>(clw, clb, out);
}

// round 6
// speedup vs baseline: 1.3208x; 1.3208x over previous
#include <cuda_runtime.h>
#include <cstdint>

#define NN 50000
#define EE 800000
#define RR 4
#define CC 4
#define GG 512

// ---------------- device scratch (static, no allocation) ----------------
__device__ float g_Wt1[320 * 64];                   // Wt[c][k], tf32-rounded bits
__device__ float g_Wt2[320 * 64];
__device__ float g_h[(size_t)RR * NN * 64];         // per-relation transformed nodes
__device__ float g_agg1[(size_t)NN * 64];           // self+bias then += scaled messages
__device__ float g_agg2[(size_t)NN * 64];
__device__ float g_cnt[RR * NN];
__device__ float g_inv[RR * NN];
__device__ int   g_deg[NN];
__device__ int   g_off[NN + 1];
__device__ int   g_fill[NN];
__device__ unsigned g_eperm[EE];                    // (et<<16)|src grouped by dst
__device__ float g_pool[GG * 64];
__device__ float g_pcnt[GG];

__device__ __forceinline__ uint32_t f2tf32(float x) {
    uint32_t u;
    asm("cvt.rna.tf32.f32 %0, %1;" : "=r"(u) : "f"(x));
    return u;
}

// ---------------- weight prep (transposed + tf32 rounded): Wt[c][k] -----------
__global__ void prep_wt(const float* __restrict__ b1, const float* __restrict__ c1,
                        const float* __restrict__ r1, const float* __restrict__ b2,
                        const float* __restrict__ c2, const float* __restrict__ r2) {
    int t = blockIdx.x * blockDim.x + threadIdx.x;
    if (t >= 2 * 320 * 64) return;
    int layer = t / 20480;
    int i = t % 20480;
    int c = i / 64;
    int k = i % 64;
    const float* basis = layer ? b2 : b1;
    const float* comp  = layer ? c2 : c1;
    const float* root  = layer ? r2 : r1;
    float v;
    if (c < 256) {
        int r = c >> 6, o = c & 63;
        v = 0.f;
#pragma unroll
        for (int b = 0; b < 4; b++)
            v += comp[r * 4 + b] * basis[((size_t)b * 64 + k) * 64 + o];
    } else {
        v = root[k * 64 + (c - 256)];
    }
    (layer ? g_Wt2 : g_Wt1)[c * 64 + k] = __uint_as_float(f2tf32(v));
}

// ---------------- zero the small accumulators ----------------
__global__ void zero_small() {
    int t = blockIdx.x * blockDim.x + threadIdx.x;
    int stride = gridDim.x * blockDim.x;
    for (int i = t; i < RR * NN; i += stride) g_cnt[i] = 0.f;
    for (int i = t; i < NN; i += stride) g_fill[i] = 0;
    for (int i = t; i < GG * 64; i += stride) g_pool[i] = 0.f;
    for (int i = t; i < GG; i += stride) g_pcnt[i] = 0.f;
}

__global__ void count_edges(const int* __restrict__ dst, const int* __restrict__ et) {
    int e = blockIdx.x * blockDim.x + threadIdx.x;
    if (e >= EE) return;
    atomicAdd(&g_cnt[et[e] * NN + dst[e]], 1.0f);
}

__global__ void invert_cnt() {
    int i = blockIdx.x * blockDim.x + threadIdx.x;
    if (i < RR * NN) g_inv[i] = 1.0f / fmaxf(g_cnt[i], 1.0f);
    if (i < NN) {
        float s = g_cnt[i] + g_cnt[NN + i] + g_cnt[2 * NN + i] + g_cnt[3 * NN + i];
        g_deg[i] = (int)s;
    }
}

__global__ void __launch_bounds__(1024) scan_deg() {
    __shared__ int sums[1024];
    const int CH = (NN + 1023) / 1024;
    int t = threadIdx.x;
    int base = t * CH;
    int local = 0;
    for (int i = 0; i < CH; i++) {
        int idx = base + i;
        if (idx < NN) local += g_deg[idx];
    }
    sums[t] = local;
    __syncthreads();
    for (int s = 1; s < 1024; s <<= 1) {
        int v = (t >= s) ? sums[t - s] : 0;
        __syncthreads();
        sums[t] += v;
        __syncthreads();
    }
    int running = sums[t] - local;
    for (int i = 0; i < CH; i++) {
        int idx = base + i;
        if (idx < NN) {
            g_off[idx] = running;
            running += g_deg[idx];
        }
    }
    if (t == 1023) g_off[NN] = sums[1023];
}

__global__ void build_perm(const int* __restrict__ src, const int* __restrict__ dst,
                           const int* __restrict__ et) {
    int e = blockIdx.x * blockDim.x + threadIdx.x;
    if (e >= EE) return;
    int d = dst[e];
    int pos = g_off[d] + atomicAdd(&g_fill[d], 1);
    g_eperm[pos] = ((unsigned)et[e] << 16) | (unsigned)src[e];
}

// ================= tf32 mma.sync GEMM: [128,64] @ [64,320] per CTA =================
// 8 warps; warp w handles rows w*16..w*16+15, all 320 cols in 5 chunks of 64.
#define SPAD 68
#define AS_FLOATS (128 * SPAD)
#define BS_FLOATS (320 * SPAD)
#define GEMM_SMEM ((AS_FLOATS + BS_FLOATS) * 4)

__global__ void __launch_bounds__(256)
gemm_tc(const float* __restrict__ Xin, const float* __restrict__ bias, int layer) {
    extern __shared__ float smem[];
    float* As = smem;                  // [128][68]  As[row][k]  (tf32 bits)
    float* Bs = smem + AS_FLOATS;      // [320][68]  Bs[c][k]    (tf32 bits)
    __shared__ float s_bias[64];

    const float* X = layer ? g_agg1 : Xin;
    const float* W = layer ? g_Wt2 : g_Wt1;
    float* aggOut = layer ? g_agg2 : g_agg1;
    const bool doRelu = (layer == 1);

    int t = threadIdx.x;
    int wid = t >> 5, lane = t & 31;
    int nodeBase = blockIdx.x * 128;
    if (t < 64) s_bias[t] = bias[t];

    // ---- A tile: 128 rows x 64 k, relu + tf32 round ----
#pragma unroll
    for (int i = 0; i < 8; i++) {
        int f = t + i * 256;           // 0..2047 float4s
        int row = f >> 4;
        int k4 = (f & 15) << 2;
        int gn = nodeBase + row;
        float4 v = make_float4(0.f, 0.f, 0.f, 0.f);
        if (gn < NN) v = *(const float4*)(X + (size_t)gn * 64 + k4);
        if (doRelu) {
            v.x = fmaxf(v.x, 0.f); v.y = fmaxf(v.y, 0.f);
            v.z = fmaxf(v.z, 0.f); v.w = fmaxf(v.w, 0.f);
        }
        float* d = As + row * SPAD + k4;
        d[0] = __uint_as_float(f2tf32(v.x));
        d[1] = __uint_as_float(f2tf32(v.y));
        d[2] = __uint_as_float(f2tf32(v.z));
        d[3] = __uint_as_float(f2tf32(v.w));
    }
    // ---- B tile: 320 rows x 64 k (already tf32 bits) ----
#pragma unroll
    for (int i = 0; i < 20; i++) {
        int f = t + i * 256;           // 0..5119 float4s
        int row = f >> 4;
        int k4 = (f & 15) << 2;
        *(float4*)(Bs + row * SPAD + k4) = *(const float4*)(W + (size_t)row * 64 + k4);
    }
    __syncthreads();

    int qrow = lane >> 2;              // 0..7
    int qcol = lane & 3;               // 0..3
    const float* Abase = As + (wid * 16 + qrow) * SPAD + qcol;
    const float* Bbase = Bs + qrow * SPAD + qcol;

#pragma unroll
    for (int j = 0; j < 5; j++) {
        float c[8][4];
#pragma unroll
        for (int nt = 0; nt < 8; nt++)
#pragma unroll
            for (int q = 0; q < 4; q++) c[nt][q] = 0.f;

#pragma unroll
        for (int ks = 0; ks < 8; ks++) {
            int k = ks * 8;
            uint32_t a0 = __float_as_uint(Abase[k]);
            uint32_t a1 = __float_as_uint(Abase[8 * SPAD + k]);
            uint32_t a2 = __float_as_uint(Abase[k + 4]);
            uint32_t a3 = __float_as_uint(Abase[8 * SPAD + k + 4]);
#pragma unroll
            for (int nt = 0; nt < 8; nt++) {
                const float* bp = Bbase + (j * 64 + nt * 8) * SPAD + k;
                uint32_t b0 = __float_as_uint(bp[0]);
                uint32_t b1 = __float_as_uint(bp[4]);
                asm volatile(
                    "mma.sync.aligned.m16n8k8.row.col.f32.tf32.tf32.f32 "
                    "{%0,%1,%2,%3}, {%4,%5,%6,%7}, {%8,%9}, {%0,%1,%2,%3};"
                    : "+f"(c[nt][0]), "+f"(c[nt][1]), "+f"(c[nt][2]), "+f"(c[nt][3])
                    : "r"(a0), "r"(a1), "r"(a2), "r"(a3), "r"(b0), "r"(b1));
            }
        }

        // ---- epilogue for chunk j ----
        int node0 = nodeBase + wid * 16 + qrow;
        int node1 = node0 + 8;
        if (j < 4) {
            float* h0 = g_h + ((size_t)j * NN + node0) * 64 + qcol * 2;
            float* h1 = g_h + ((size_t)j * NN + node1) * 64 + qcol * 2;
#pragma unroll
            for (int nt = 0; nt < 8; nt++) {
                if (node0 < NN) *(float2*)(h0 + nt * 8) = make_float2(c[nt][0], c[nt][1]);
                if (node1 < NN) *(float2*)(h1 + nt * 8) = make_float2(c[nt][2], c[nt][3]);
            }
        } else {
            float* a0p = aggOut + (size_t)node0 * 64 + qcol * 2;
            float* a1p = aggOut + (size_t)node1 * 64 + qcol * 2;
#pragma unroll
            for (int nt = 0; nt < 8; nt++) {
                float bx = s_bias[nt * 8 + qcol * 2];
                float by = s_bias[nt * 8 + qcol * 2 + 1];
                if (node0 < NN) *(float2*)(a0p + nt * 8) = make_float2(c[nt][0] + bx, c[nt][1] + by);
                if (node1 < NN) *(float2*)(a1p + nt * 8) = make_float2(c[nt][2] + bx, c[nt][3] + by);
            }
        }
    }
}

// ---------------- segmented aggregation: one warp per dst, 4-way unroll --------
__global__ void __launch_bounds__(256) agg_edges(int layer) {
    int w = (blockIdx.x * blockDim.x + threadIdx.x) >> 5;
    if (w >= NN) return;
    int lane = threadIdx.x & 31;
    int beg = g_off[w], end = g_off[w + 1];
    float* agg = (layer ? g_agg2 : g_agg1) + (size_t)w * 64 + lane * 2;
    float2 a0 = *(float2*)agg;
    float2 a1 = make_float2(0.f, 0.f);
    float2 a2 = make_float2(0.f, 0.f);
    float2 a3 = make_float2(0.f, 0.f);

    int e = beg;
    for (; e + 3 < end; e += 4) {
        unsigned p0 = g_eperm[e], p1 = g_eperm[e + 1];
        unsigned p2 = g_eperm[e + 2], p3 = g_eperm[e + 3];
        float i0 = g_inv[(p0 >> 16) * NN + w];
        float i1 = g_inv[(p1 >> 16) * NN + w];
        float i2 = g_inv[(p2 >> 16) * NN + w];
        float i3 = g_inv[(p3 >> 16) * NN + w];
        float2 v0 = *(const float2*)(g_h + (((size_t)(p0 >> 16)) * NN + (p0 & 0xFFFF)) * 64 + lane * 2);
        float2 v1 = *(const float2*)(g_h + (((size_t)(p1 >> 16)) * NN + (p1 & 0xFFFF)) * 64 + lane * 2);
        float2 v2 = *(const float2*)(g_h + (((size_t)(p2 >> 16)) * NN + (p2 & 0xFFFF)) * 64 + lane * 2);
        float2 v3 = *(const float2*)(g_h + (((size_t)(p3 >> 16)) * NN + (p3 & 0xFFFF)) * 64 + lane * 2);
        a0.x += v0.x * i0; a0.y += v0.y * i0;
        a1.x += v1.x * i1; a1.y += v1.y * i1;
        a2.x += v2.x * i2; a2.y += v2.y * i2;
        a3.x += v3.x * i3; a3.y += v3.y * i3;
    }
    for (; e < end; e++) {
        unsigned p = g_eperm[e];
        float iv = g_inv[(p >> 16) * NN + w];
        float2 v = *(const float2*)(g_h + (((size_t)(p >> 16)) * NN + (p & 0xFFFF)) * 64 + lane * 2);
        a0.x += v.x * iv; a0.y += v.y * iv;
    }
    a0.x += a1.x + a2.x + a3.x;
    a0.y += a1.y + a2.y + a3.y;
    *(float2*)agg = a0;
}

// ---------------- final: relu(agg2), pool per graph ----------------
__global__ void pool_final(const int* __restrict__ batch) {
    int t = blockIdx.x * blockDim.x + threadIdx.x;
    int n = t >> 4;
    if (n >= NN) return;
    int j = t & 15;
    float4 o = *(const float4*)(g_agg2 + (size_t)n * 64 + j * 4);
    o.x = fmaxf(o.x, 0.f); o.y = fmaxf(o.y, 0.f);
    o.z = fmaxf(o.z, 0.f); o.w = fmaxf(o.w, 0.f);
    int g = batch[n];
    float* p = g_pool + g * 64 + j * 4;
    asm volatile("red.global.add.v4.f32 [%0], {%1,%2,%3,%4};"
                 :: "l"(p), "f"(o.x), "f"(o.y), "f"(o.z), "f"(o.w) : "memory");
    if (j == 0) atomicAdd(&g_pcnt[g], 1.0f);
}

// ---------------- classifier ----------------
__global__ void classify(const float* __restrict__ w, const float* __restrict__ b,
                         float* __restrict__ out) {
    int t = blockIdx.x * blockDim.x + threadIdx.x;
    if (t >= GG * CC) return;
    int g = t / CC, c = t % CC;
    float inv = 1.f / fmaxf(g_pcnt[g], 1.f);
    float acc = b[c];
#pragma unroll
    for (int k = 0; k < 64; k++)
        acc += g_pool[g * 64 + k] * inv * w[k * CC + c];
    out[t] = acc;
}

// ---------------- launch ----------------
extern "C" void kernel_launch(void* const* d_in, const int* in_sizes, int n_in,
                              void* d_out, int out_size) {
    const float* x      = (const float*)d_in[0];
    const int*   ei     = (const int*)d_in[1];
    const int*   et     = (const int*)d_in[2];
    const int*   batch  = (const int*)d_in[3];
    const float* basis1 = (const float*)d_in[4];
    const float* comp1  = (const float*)d_in[5];
    const float* root1  = (const float*)d_in[6];
    const float* bias1  = (const float*)d_in[7];
    const float* basis2 = (const float*)d_in[8];
    const float* comp2  = (const float*)d_in[9];
    const float* root2  = (const float*)d_in[10];
    const float* bias2  = (const float*)d_in[11];
    const float* clw    = (const float*)d_in[12];
    const float* clb    = (const float*)d_in[13];
    float* out = (float*)d_out;

    const int* src = ei;
    const int* dstp = ei + EE;

    static int attr_set = 0;
    if (!attr_set) {
        cudaFuncSetAttribute(gemm_tc, cudaFuncAttributeMaxDynamicSharedMemorySize,
                             GEMM_SMEM);
        attr_set = 1;
    }

    // ---- per-launch preprocessing ----
    zero_small<<<256, 256>>>();
    prep_wt<<<160, 256>>>(basis1, comp1, root1, basis2, comp2, root2);
    count_edges<<<EE / 256, 256>>>(dstp, et);
    invert_cnt<<<(RR * NN + 255) / 256, 256>>>();
    scan_deg<<<1, 1024>>>();
    build_perm<<<EE / 256, 256>>>(src, dstp, et);

    int gblocks = (NN + 127) / 128;   // 391

    // ---- layer 1 ----
    gemm_tc<<<gblocks, 256, GEMM_SMEM>>>(x, bias1, 0);
    agg_edges<<<(NN * 32 + 255) / 256, 256>>>(0);

    // ---- layer 2 ----
    gemm_tc<<<gblocks, 256, GEMM_SMEM>>>(x, bias2, 1);
    agg_edges<<<(NN * 32 + 255) / 256, 256>>>(1);

    // ---- pool + classifier ----
    pool_final<<<(NN * 16) / 256, 256>>>(batch);
    classify<<<(GG * CC + 255) / 256, 256>>>(clw, clb, out);
}